// round 7
// baseline (speedup 1.0000x reference)
#include <cuda_runtime.h>
#include <cuda_fp16.h>
#include <math.h>
#include <stdint.h>

// ---------------- Problem constants ----------------
#define T_TOKENS 16384
#define D_MODEL  4096
#define N_EXP    128

// ---------------- GEMM config ----------------
#define BM   128
#define BN   128
#define CK   64                 // K per chunk (64 fp16 = 128B row)
#define NCHUNK (D_MODEL / CK)   // 64
#define TPB  320                // 8 consumer warps (2x4) + 2 producer warps

// smem: two 64KB stages; each: Ah Al Bh Bl (16KB each, 128 rows x 128B)
#define STAGE_BYTES 65536
#define OFF_AH 0
#define OFF_AL 16384
#define OFF_BH 32768
#define OFF_BL 49152
#define SMEM_TOTAL (2 * STAGE_BYTES)   // 131072

#define LS_STRIDE 132
#define L_SCALE   1024.0f
#define L_INV     (1.0f / 1024.0f)
#define SWZ(b) ((b) ^ (((b) >> 3) & 0x70))

// Named barriers (count = all 320 threads)
#define BAR_FULL0  1
#define BAR_FULL1  2
#define BAR_EMPTY0 3
#define BAR_EMPTY1 4
#define BAR_SYNC(id)   asm volatile("bar.sync %0, %1;"   :: "r"(id), "r"(TPB) : "memory")
#define BAR_ARRIVE(id) asm volatile("bar.arrive %0, %1;" :: "r"(id), "r"(TPB) : "memory")

// ---------------- sm_80-level PTX helpers ----------------
__device__ __forceinline__ uint32_t smem_to_u32(const void* p) {
    uint32_t a;
    asm("{ .reg .u64 t; cvta.to.shared.u64 t, %1; cvt.u32.u64 %0, t; }"
        : "=r"(a) : "l"(p));
    return a;
}
#define LDSM4(r0, r1, r2, r3, addr) \
    asm volatile("ldmatrix.sync.aligned.m8n8.x4.shared.b16 {%0,%1,%2,%3}, [%4];" \
        : "=r"(r0), "=r"(r1), "=r"(r2), "=r"(r3) : "r"(addr))
#define MMA16816(c, a, b0, b1) \
    asm volatile("mma.sync.aligned.m16n8k16.row.col.f32.f16.f16.f32 " \
        "{%0,%1,%2,%3},{%4,%5,%6,%7},{%8,%9},{%0,%1,%2,%3};" \
        : "+f"((c)[0]), "+f"((c)[1]), "+f"((c)[2]), "+f"((c)[3]) \
        : "r"((a)[0]), "r"((a)[1]), "r"((a)[2]), "r"((a)[3]), "r"(b0), "r"(b1))
__device__ __forceinline__ void cp16(uint32_t dst, const void* src) {
    asm volatile("cp.async.cg.shared.global [%0], [%1], 16;"
                 :: "r"(dst), "l"(src));
}
#define CP_COMMIT() asm volatile("cp.async.commit_group;" ::: "memory")
#define CP_WAIT0()  asm volatile("cp.async.wait_group 0;" ::: "memory")

// ---------------- Global scratch ----------------
__device__ float g_me[N_EXP];
__device__ int   g_ce[N_EXP];
__device__ __half g_Bh[N_EXP * D_MODEL];
__device__ __half g_Bl[N_EXP * D_MODEL];

__global__ void init_kernel() {
    int i = threadIdx.x;
    if (i < N_EXP) { g_me[i] = 0.0f; g_ce[i] = 0; }
}

// fp16 2-way split: f = h + (l / 1024), l stored pre-scaled by 1024
__device__ __forceinline__ void split2(float f, __half& h, __half& l) {
    h = __float2half_rn(f);
    l = __float2half_rn((f - __half2float(h)) * L_SCALE);
}
__device__ __forceinline__ uint32_t pack2h(__half a, __half b) {
    return (uint32_t)__half_as_ushort(a) |
           ((uint32_t)__half_as_ushort(b) << 16);
}

__global__ void prep_b_kernel(const float* __restrict__ wg) {
    int idx = blockIdx.x * blockDim.x + threadIdx.x;  // 0..131071
    float4 v = ((const float4*)wg)[idx];
    float f[4] = {v.x, v.y, v.z, v.w};
    __half h[4], l[4];
#pragma unroll
    for (int q = 0; q < 4; q++) split2(f[q], h[q], l[q]);
    ((uint2*)g_Bh)[idx] = make_uint2(pack2h(h[0], h[1]), pack2h(h[2], h[3]));
    ((uint2*)g_Bl)[idx] = make_uint2(pack2h(l[0], l[1]), pack2h(l[2], l[3]));
}

// top-2: (v1,i1) >= (v2,i2); ties -> smaller index (jax top_k semantics)
__device__ __forceinline__ void top2_upd(float& v1, int& i1, float& v2, int& i2,
                                         float v, int i) {
    if (v > v1 || (v == v1 && i < i1)) {
        v2 = v1; i2 = i1; v1 = v; i1 = i;
    } else if (v > v2 || (v == v2 && i < i2)) {
        v2 = v; i2 = i;
    }
}

__global__ void __launch_bounds__(TPB, 1)
gate_kernel(const float* __restrict__ A, float* __restrict__ out) {
    extern __shared__ char smem[];
    const uint32_t smem_u = smem_to_u32(smem);
    const int tid  = threadIdx.x;
    const int wid  = tid >> 5;
    const int lane = tid & 31;
    const int row0 = blockIdx.x * BM;

    float acc0[4][4][4];   // hh products
    float acc1[4][4][4];   // (h*l + l*h) products, carries x1024 scale

    if (wid < 8) {
        // ================= CONSUMERS: 2(M) x 4(N) warp grid =================
        const int mw = wid >> 2;
        const int nw = wid & 3;
        const int a_mrow = (lane & 7) + ((lane >> 3) & 1) * 8;
        const int a_cofs = ((lane >> 4) & 1) * 16;
        const int b_nrow = (lane & 7) + ((lane >> 4) & 1) * 8;
        const int b_cofs = ((lane >> 3) & 1) * 16;

#pragma unroll
        for (int i = 0; i < 4; i++)
#pragma unroll
            for (int j = 0; j < 4; j++)
#pragma unroll
                for (int q = 0; q < 4; q++) { acc0[i][j][q] = 0.0f; acc1[i][j][q] = 0.0f; }

        for (int c = 0; c < NCHUNK; c++) {
            const int s = c & 1;
            const uint32_t cur = smem_u + s * STAGE_BYTES;
            BAR_SYNC(s == 0 ? BAR_FULL0 : BAR_FULL1);

#pragma unroll 1
            for (int ks = 0; ks < 4; ks++) {
                const int kb = ks * 32;
                // B fragments: h and l parts
                uint32_t bfh[8], bfl[8];
#pragma unroll
                for (int q = 0; q < 2; q++) {
                    uint32_t bsw = SWZ((uint32_t)((nw * 32 + q * 16 + b_nrow) * 128 + kb + b_cofs));
                    LDSM4(bfh[q*4+0], bfh[q*4+1], bfh[q*4+2], bfh[q*4+3], cur + OFF_BH + bsw);
                    LDSM4(bfl[q*4+0], bfl[q*4+1], bfl[q*4+2], bfl[q*4+3], cur + OFF_BL + bsw);
                }
                // A-h fragments
                uint32_t af[16];
#pragma unroll
                for (int tm = 0; tm < 4; tm++) {
                    uint32_t asw = SWZ((uint32_t)((mw * 64 + tm * 16 + a_mrow) * 128 + kb + a_cofs));
                    LDSM4(af[tm*4+0], af[tm*4+1], af[tm*4+2], af[tm*4+3], cur + OFF_AH + asw);
                }
                // hh -> acc0 ; h*bl -> acc1
#pragma unroll
                for (int tm = 0; tm < 4; tm++)
#pragma unroll
                    for (int tn = 0; tn < 4; tn++) {
                        int bq = (tn >> 1) * 4 + (tn & 1) * 2;
                        MMA16816(acc0[tm][tn], &af[tm*4], bfh[bq], bfh[bq+1]);
                        MMA16816(acc1[tm][tn], &af[tm*4], bfl[bq], bfl[bq+1]);
                    }
                // A-l fragments (reuse af regs)
#pragma unroll
                for (int tm = 0; tm < 4; tm++) {
                    uint32_t asw = SWZ((uint32_t)((mw * 64 + tm * 16 + a_mrow) * 128 + kb + a_cofs));
                    LDSM4(af[tm*4+0], af[tm*4+1], af[tm*4+2], af[tm*4+3], cur + OFF_AL + asw);
                }
                // al*bh -> acc1
#pragma unroll
                for (int tm = 0; tm < 4; tm++)
#pragma unroll
                    for (int tn = 0; tn < 4; tn++) {
                        int bq = (tn >> 1) * 4 + (tn & 1) * 2;
                        MMA16816(acc1[tm][tn], &af[tm*4], bfh[bq], bfh[bq+1]);
                    }
            }
            BAR_ARRIVE(s == 0 ? BAR_EMPTY0 : BAR_EMPTY1);
        }
    } else {
        // ================= PRODUCERS: 2 warps, 64 threads =================
        const int ptid = tid - 256;   // 0..63
        for (int c = 0; c < NCHUNK; c++) {
            const int s = c & 1;
            char* stg = smem + s * STAGE_BYTES;
            const uint32_t stg_u = smem_u + s * STAGE_BYTES;
            const int k0 = c * CK;

            if (c >= 2) BAR_SYNC(s == 0 ? BAR_EMPTY0 : BAR_EMPTY1);

            // B tiles via cp.async (in flight during A work)
#pragma unroll
            for (int i = 0; i < 16; i++) {
                int idx = ptid + i * 64;           // 0..1023
                int r   = idx >> 3;
                int c16 = (idx & 7) * 16;
                size_t g = (size_t)r * D_MODEL + k0 + (c16 >> 1);
                uint32_t sw = SWZ((uint32_t)(r * 128 + c16));
                cp16(stg_u + OFF_BH + sw, g_Bh + g);
                cp16(stg_u + OFF_BL + sw, g_Bl + g);
            }
            CP_COMMIT();

            // A: LDG -> split2 -> STS, two batches of 16 float4
#pragma unroll
            for (int bat = 0; bat < 2; bat++) {
                float4 aval[16];
#pragma unroll
                for (int i = 0; i < 16; i++) {
                    int idx = ptid + (bat * 16 + i) * 64;   // 0..2047
                    int r   = idx >> 4;
                    int col = (idx & 15) << 2;
                    aval[i] = *(const float4*)(A + (size_t)(row0 + r) * D_MODEL + k0 + col);
                }
#pragma unroll
                for (int i = 0; i < 16; i++) {
                    int idx = ptid + (bat * 16 + i) * 64;
                    int r   = idx >> 4;
                    int col = (idx & 15) << 2;
                    float f[4] = {aval[i].x, aval[i].y, aval[i].z, aval[i].w};
                    __half h[4], l[4];
#pragma unroll
                    for (int q = 0; q < 4; q++) split2(f[q], h[q], l[q]);
                    uint32_t sw = SWZ((uint32_t)(r * 128 + col * 2));
                    *(uint2*)(stg + OFF_AH + sw) = make_uint2(pack2h(h[0], h[1]), pack2h(h[2], h[3]));
                    *(uint2*)(stg + OFF_AL + sw) = make_uint2(pack2h(l[0], l[1]), pack2h(l[2], l[3]));
                }
            }
            CP_WAIT0();
            BAR_ARRIVE(s == 0 ? BAR_FULL0 : BAR_FULL1);
        }
    }

    __syncthreads();   // all threads; stages now free -> repurpose as Ls

    float* Ls  = (float*)smem;
    float* sMe = (float*)(smem + BM * LS_STRIDE * 4);

    if (wid < 8) {
        const int mw = wid >> 2, nw = wid & 3;
        const int gid = lane >> 2, tig = lane & 3;
#pragma unroll
        for (int tm = 0; tm < 4; tm++)
#pragma unroll
            for (int tn = 0; tn < 4; tn++) {
                int r_ = mw * 64 + tm * 16 + gid;
                int c_ = nw * 32 + tn * 8 + tig * 2;
                Ls[r_ * LS_STRIDE + c_]           = acc0[tm][tn][0] + acc1[tm][tn][0] * L_INV;
                Ls[r_ * LS_STRIDE + c_ + 1]       = acc0[tm][tn][1] + acc1[tm][tn][1] * L_INV;
                Ls[(r_ + 8) * LS_STRIDE + c_]     = acc0[tm][tn][2] + acc1[tm][tn][2] * L_INV;
                Ls[(r_ + 8) * LS_STRIDE + c_ + 1] = acc0[tm][tn][3] + acc1[tm][tn][3] * L_INV;
            }
    } else {
        if (tid - 256 < N_EXP) sMe[tid - 256] = 0.0f;
        if (tid - 256 + 64 < N_EXP) sMe[tid - 256 + 64] = 0.0f;
    }
    __syncthreads();

    // ---- epilogue: one warp per token, 10 warps stride over 128 tokens ----
    const float inv_temp = 1.0f / 0.3f;
    for (int t = wid; t < BM; t += 10) {
        float v[4]; int ix[4];
#pragma unroll
        for (int q = 0; q < 4; q++) {
            ix[q] = lane + q * 32;
            v[q]  = Ls[t * LS_STRIDE + ix[q]];
        }
        float v1 = -INFINITY, v2 = -INFINITY;
        int   i1 = N_EXP, i2 = N_EXP;
#pragma unroll
        for (int q = 0; q < 4; q++) top2_upd(v1, i1, v2, i2, v[q], ix[q]);
#pragma unroll
        for (int off = 16; off > 0; off >>= 1) {
            float ov1 = __shfl_xor_sync(0xffffffffu, v1, off);
            int   oi1 = __shfl_xor_sync(0xffffffffu, i1, off);
            float ov2 = __shfl_xor_sync(0xffffffffu, v2, off);
            int   oi2 = __shfl_xor_sync(0xffffffffu, i2, off);
            top2_upd(v1, i1, v2, i2, ov1, oi1);
            top2_upd(v1, i1, v2, i2, ov2, oi2);
        }
        float p[4], zl = 0.0f;
#pragma unroll
        for (int q = 0; q < 4; q++) {
            p[q] = expf((v[q] - v1) * inv_temp);
            zl += p[q];
        }
#pragma unroll
        for (int off = 16; off > 0; off >>= 1)
            zl += __shfl_xor_sync(0xffffffffu, zl, off);
        float invZ = 1.0f / zl;
#pragma unroll
        for (int q = 0; q < 4; q++)
            atomicAdd(&sMe[ix[q]], p[q] * invZ);

        if (lane == 0) {
            int tok = row0 + t;
            out[tok * 2 + 0] = (float)i1;
            out[tok * 2 + 1] = (float)i2;
            float e  = expf(v2 - v1);
            float g1 = e / (1.0f + e);
            out[2 * T_TOKENS + tok * 2 + 0] = 1.0f - g1;
            out[2 * T_TOKENS + tok * 2 + 1] = g1;
            atomicAdd(&g_ce[i1], 1);
        }
    }
    __syncthreads();
    if (tid < N_EXP) atomicAdd(&g_me[tid], sMe[tid]);
}

__global__ void loss_kernel(float* __restrict__ out) {
    __shared__ float red[N_EXP];
    int i = threadIdx.x;
    red[i] = g_me[i] * (float)g_ce[i];
    __syncthreads();
    for (int s = 64; s > 0; s >>= 1) {
        if (i < s) red[i] += red[i + s];
        __syncthreads();
    }
    if (i == 0) {
        out[4 * T_TOKENS] = red[0] * ((float)N_EXP /
                              ((float)T_TOKENS * (float)T_TOKENS));
    }
}

extern "C" void kernel_launch(void* const* d_in, const int* in_sizes, int n_in,
                              void* d_out, int out_size) {
    const float* inp = (const float*)d_in[0];
    const float* wg  = (const float*)d_in[1];
    float* out = (float*)d_out;

    prep_b_kernel<<<(N_EXP * D_MODEL / 4 + 255) / 256, 256>>>(wg);
    init_kernel<<<1, 128>>>();

    cudaFuncSetAttribute(gate_kernel,
                         cudaFuncAttributeMaxDynamicSharedMemorySize,
                         SMEM_TOTAL);
    gate_kernel<<<T_TOKENS / BM, TPB, SMEM_TOTAL>>>(inp, out);

    loss_kernel<<<1, N_EXP>>>(out);
}

// round 8
// speedup vs baseline: 1.4776x; 1.4776x over previous
#include <cuda_runtime.h>
#include <cuda_fp16.h>
#include <math.h>
#include <stdint.h>

// ---------------- Problem constants ----------------
#define T_TOKENS 16384
#define D_MODEL  4096
#define N_EXP    128

// ---------------- GEMM config ----------------
#define BM   128
#define BN   128
#define CK   64                 // K per chunk (64 fp16 = 128B row)
#define NCHUNK (D_MODEL / CK)   // 64
#define TPB  384                // 8 consumer warps (2x4) + 4 producer warps

// smem: two 64KB stages; each: Ah Al Bh Bl (16KB each, 128 rows x 128B)
#define STAGE_BYTES 65536
#define OFF_AH 0
#define OFF_AL 16384
#define OFF_BH 32768
#define OFF_BL 49152
#define SMEM_TOTAL (2 * STAGE_BYTES)   // 131072

#define LS_STRIDE 132
#define SWZ(b) ((b) ^ (((b) >> 3) & 0x70))

// Named barriers (count = all 384 threads)
#define BAR_FULL0  1
#define BAR_FULL1  2
#define BAR_EMPTY0 3
#define BAR_EMPTY1 4
#define BAR_SYNC(id)   asm volatile("bar.sync %0, %1;"   :: "r"(id), "r"(TPB) : "memory")
#define BAR_ARRIVE(id) asm volatile("bar.arrive %0, %1;" :: "r"(id), "r"(TPB) : "memory")

// ---------------- sm_80-level PTX helpers ----------------
__device__ __forceinline__ uint32_t smem_to_u32(const void* p) {
    uint32_t a;
    asm("{ .reg .u64 t; cvta.to.shared.u64 t, %1; cvt.u32.u64 %0, t; }"
        : "=r"(a) : "l"(p));
    return a;
}
#define LDSM4(r0, r1, r2, r3, addr) \
    asm volatile("ldmatrix.sync.aligned.m8n8.x4.shared.b16 {%0,%1,%2,%3}, [%4];" \
        : "=r"(r0), "=r"(r1), "=r"(r2), "=r"(r3) : "r"(addr))
#define MMA16816(c, a, b0, b1) \
    asm volatile("mma.sync.aligned.m16n8k16.row.col.f32.f16.f16.f32 " \
        "{%0,%1,%2,%3},{%4,%5,%6,%7},{%8,%9},{%0,%1,%2,%3};" \
        : "+f"((c)[0]), "+f"((c)[1]), "+f"((c)[2]), "+f"((c)[3]) \
        : "r"((a)[0]), "r"((a)[1]), "r"((a)[2]), "r"((a)[3]), "r"(b0), "r"(b1))
__device__ __forceinline__ void cp16(uint32_t dst, const void* src) {
    asm volatile("cp.async.cg.shared.global [%0], [%1], 16;"
                 :: "r"(dst), "l"(src));
}
#define CP_COMMIT() asm volatile("cp.async.commit_group;" ::: "memory")
#define CP_WAIT0()  asm volatile("cp.async.wait_group 0;" ::: "memory")

// ---------------- Global scratch ----------------
__device__ float g_me[N_EXP];
__device__ int   g_ce[N_EXP];
__device__ __half g_Bh[N_EXP * D_MODEL];
__device__ __half g_Bl[N_EXP * D_MODEL];

__global__ void init_kernel() {
    int i = threadIdx.x;
    if (i < N_EXP) { g_me[i] = 0.0f; g_ce[i] = 0; }
}

// fp16 2-way split, UNSCALED residual: f = h + l exactly (l may be subnormal)
__device__ __forceinline__ void split2(float f, __half& h, __half& l) {
    h = __float2half_rn(f);
    l = __float2half_rn(f - __half2float(h));
}
__device__ __forceinline__ uint32_t pack2h(__half a, __half b) {
    return (uint32_t)__half_as_ushort(a) |
           ((uint32_t)__half_as_ushort(b) << 16);
}

__global__ void prep_b_kernel(const float* __restrict__ wg) {
    int idx = blockIdx.x * blockDim.x + threadIdx.x;  // 0..131071
    float4 v = ((const float4*)wg)[idx];
    float f[4] = {v.x, v.y, v.z, v.w};
    __half h[4], l[4];
#pragma unroll
    for (int q = 0; q < 4; q++) split2(f[q], h[q], l[q]);
    ((uint2*)g_Bh)[idx] = make_uint2(pack2h(h[0], h[1]), pack2h(h[2], h[3]));
    ((uint2*)g_Bl)[idx] = make_uint2(pack2h(l[0], l[1]), pack2h(l[2], l[3]));
}

// top-2: (v1,i1) >= (v2,i2); ties -> smaller index (jax top_k semantics)
__device__ __forceinline__ void top2_upd(float& v1, int& i1, float& v2, int& i2,
                                         float v, int i) {
    if (v > v1 || (v == v1 && i < i1)) {
        v2 = v1; i2 = i1; v1 = v; i1 = i;
    } else if (v > v2 || (v == v2 && i < i2)) {
        v2 = v; i2 = i;
    }
}

__global__ void __launch_bounds__(TPB, 1)
gate_kernel(const float* __restrict__ A, float* __restrict__ out) {
    extern __shared__ char smem[];
    const uint32_t smem_u = smem_to_u32(smem);
    const int tid  = threadIdx.x;
    const int wid  = tid >> 5;
    const int lane = tid & 31;
    const int row0 = blockIdx.x * BM;

    float acc[4][4][4];   // single accumulator set: all 3 products fold in

    if (wid < 8) {
        // ================= CONSUMERS: 2(M) x 4(N) warp grid =================
        const int mw = wid >> 2;
        const int nw = wid & 3;
        const int a_mrow = (lane & 7) + ((lane >> 3) & 1) * 8;
        const int a_cofs = ((lane >> 4) & 1) * 16;
        const int b_nrow = (lane & 7) + ((lane >> 4) & 1) * 8;
        const int b_cofs = ((lane >> 3) & 1) * 16;

#pragma unroll
        for (int i = 0; i < 4; i++)
#pragma unroll
            for (int j = 0; j < 4; j++)
#pragma unroll
                for (int q = 0; q < 4; q++) acc[i][j][q] = 0.0f;

        for (int c = 0; c < NCHUNK; c++) {
            const int s = c & 1;
            const uint32_t cur = smem_u + s * STAGE_BYTES;
            BAR_SYNC(s == 0 ? BAR_FULL0 : BAR_FULL1);

#pragma unroll 1
            for (int ks = 0; ks < 4; ks++) {
                const int kb = ks * 32;
                // B fragments: h and l parts
                uint32_t bfh[8], bfl[8];
#pragma unroll
                for (int q = 0; q < 2; q++) {
                    uint32_t bsw = SWZ((uint32_t)((nw * 32 + q * 16 + b_nrow) * 128 + kb + b_cofs));
                    LDSM4(bfh[q*4+0], bfh[q*4+1], bfh[q*4+2], bfh[q*4+3], cur + OFF_BH + bsw);
                    LDSM4(bfl[q*4+0], bfl[q*4+1], bfl[q*4+2], bfl[q*4+3], cur + OFF_BL + bsw);
                }
                // A-h fragments
                uint32_t af[16];
#pragma unroll
                for (int tm = 0; tm < 4; tm++) {
                    uint32_t asw = SWZ((uint32_t)((mw * 64 + tm * 16 + a_mrow) * 128 + kb + a_cofs));
                    LDSM4(af[tm*4+0], af[tm*4+1], af[tm*4+2], af[tm*4+3], cur + OFF_AH + asw);
                }
                // ah*bh and ah*bl -> acc (bl unscaled: correct magnitude)
#pragma unroll
                for (int tm = 0; tm < 4; tm++)
#pragma unroll
                    for (int tn = 0; tn < 4; tn++) {
                        int bq = (tn >> 1) * 4 + (tn & 1) * 2;
                        MMA16816(acc[tm][tn], &af[tm*4], bfh[bq], bfh[bq+1]);
                        MMA16816(acc[tm][tn], &af[tm*4], bfl[bq], bfl[bq+1]);
                    }
                // A-l fragments (reuse af regs)
#pragma unroll
                for (int tm = 0; tm < 4; tm++) {
                    uint32_t asw = SWZ((uint32_t)((mw * 64 + tm * 16 + a_mrow) * 128 + kb + a_cofs));
                    LDSM4(af[tm*4+0], af[tm*4+1], af[tm*4+2], af[tm*4+3], cur + OFF_AL + asw);
                }
                // al*bh -> acc
#pragma unroll
                for (int tm = 0; tm < 4; tm++)
#pragma unroll
                    for (int tn = 0; tn < 4; tn++) {
                        int bq = (tn >> 1) * 4 + (tn & 1) * 2;
                        MMA16816(acc[tm][tn], &af[tm*4], bfh[bq], bfh[bq+1]);
                    }
            }
            BAR_ARRIVE(s == 0 ? BAR_EMPTY0 : BAR_EMPTY1);
        }
    } else {
        // ================= PRODUCERS: 4 warps, 128 threads =================
        const int ptid = tid - 256;   // 0..127
        for (int c = 0; c < NCHUNK; c++) {
            const int s = c & 1;
            char* stg = smem + s * STAGE_BYTES;
            const uint32_t stg_u = smem_u + s * STAGE_BYTES;
            const int k0 = c * CK;

            if (c >= 2) BAR_SYNC(s == 0 ? BAR_EMPTY0 : BAR_EMPTY1);

            // B tiles via cp.async (in flight during A work)
#pragma unroll
            for (int i = 0; i < 8; i++) {
                int idx = ptid + i * 128;          // 0..1023
                int r   = idx >> 3;
                int c16 = (idx & 7) * 16;
                size_t g = (size_t)r * D_MODEL + k0 + (c16 >> 1);
                uint32_t sw = SWZ((uint32_t)(r * 128 + c16));
                cp16(stg_u + OFF_BH + sw, g_Bh + g);
                cp16(stg_u + OFF_BL + sw, g_Bl + g);
            }
            CP_COMMIT();

            // A: LDG (MLP=16) -> split2 -> STS
            float4 aval[16];
#pragma unroll
            for (int i = 0; i < 16; i++) {
                int idx = ptid + i * 128;          // 0..2047
                int r   = idx >> 4;
                int col = (idx & 15) << 2;
                aval[i] = *(const float4*)(A + (size_t)(row0 + r) * D_MODEL + k0 + col);
            }
#pragma unroll
            for (int i = 0; i < 16; i++) {
                int idx = ptid + i * 128;
                int r   = idx >> 4;
                int col = (idx & 15) << 2;
                float f[4] = {aval[i].x, aval[i].y, aval[i].z, aval[i].w};
                __half h[4], l[4];
#pragma unroll
                for (int q = 0; q < 4; q++) split2(f[q], h[q], l[q]);
                uint32_t sw = SWZ((uint32_t)(r * 128 + col * 2));
                *(uint2*)(stg + OFF_AH + sw) = make_uint2(pack2h(h[0], h[1]), pack2h(h[2], h[3]));
                *(uint2*)(stg + OFF_AL + sw) = make_uint2(pack2h(l[0], l[1]), pack2h(l[2], l[3]));
            }
            CP_WAIT0();
            BAR_ARRIVE(s == 0 ? BAR_FULL0 : BAR_FULL1);
        }
    }

    __syncthreads();   // all 384 threads; stages now free -> repurpose as Ls

    float* Ls  = (float*)smem;
    float* sMe = (float*)(smem + BM * LS_STRIDE * 4);

    if (wid < 8) {
        const int mw = wid >> 2, nw = wid & 3;
        const int gid = lane >> 2, tig = lane & 3;
#pragma unroll
        for (int tm = 0; tm < 4; tm++)
#pragma unroll
            for (int tn = 0; tn < 4; tn++) {
                int r_ = mw * 64 + tm * 16 + gid;
                int c_ = nw * 32 + tn * 8 + tig * 2;
                Ls[r_ * LS_STRIDE + c_]           = acc[tm][tn][0];
                Ls[r_ * LS_STRIDE + c_ + 1]       = acc[tm][tn][1];
                Ls[(r_ + 8) * LS_STRIDE + c_]     = acc[tm][tn][2];
                Ls[(r_ + 8) * LS_STRIDE + c_ + 1] = acc[tm][tn][3];
            }
    }
    if (tid >= 256 && tid < 256 + N_EXP) sMe[tid - 256] = 0.0f;
    __syncthreads();

    // ---- epilogue: one warp per token, 12 warps stride over 128 tokens ----
    const float inv_temp = 1.0f / 0.3f;
    for (int t = wid; t < BM; t += 12) {
        float v[4]; int ix[4];
#pragma unroll
        for (int q = 0; q < 4; q++) {
            ix[q] = lane + q * 32;
            v[q]  = Ls[t * LS_STRIDE + ix[q]];
        }
        float v1 = -INFINITY, v2 = -INFINITY;
        int   i1 = N_EXP, i2 = N_EXP;
#pragma unroll
        for (int q = 0; q < 4; q++) top2_upd(v1, i1, v2, i2, v[q], ix[q]);
#pragma unroll
        for (int off = 16; off > 0; off >>= 1) {
            float ov1 = __shfl_xor_sync(0xffffffffu, v1, off);
            int   oi1 = __shfl_xor_sync(0xffffffffu, i1, off);
            float ov2 = __shfl_xor_sync(0xffffffffu, v2, off);
            int   oi2 = __shfl_xor_sync(0xffffffffu, i2, off);
            top2_upd(v1, i1, v2, i2, ov1, oi1);
            top2_upd(v1, i1, v2, i2, ov2, oi2);
        }
        float p[4], zl = 0.0f;
#pragma unroll
        for (int q = 0; q < 4; q++) {
            p[q] = expf((v[q] - v1) * inv_temp);
            zl += p[q];
        }
#pragma unroll
        for (int off = 16; off > 0; off >>= 1)
            zl += __shfl_xor_sync(0xffffffffu, zl, off);
        float invZ = 1.0f / zl;
#pragma unroll
        for (int q = 0; q < 4; q++)
            atomicAdd(&sMe[ix[q]], p[q] * invZ);

        if (lane == 0) {
            int tok = row0 + t;
            out[tok * 2 + 0] = (float)i1;
            out[tok * 2 + 1] = (float)i2;
            float e  = expf(v2 - v1);
            float g1 = e / (1.0f + e);
            out[2 * T_TOKENS + tok * 2 + 0] = 1.0f - g1;
            out[2 * T_TOKENS + tok * 2 + 1] = g1;
            atomicAdd(&g_ce[i1], 1);
        }
    }
    __syncthreads();
    if (tid < N_EXP) atomicAdd(&g_me[tid], sMe[tid]);
}

__global__ void loss_kernel(float* __restrict__ out) {
    __shared__ float red[N_EXP];
    int i = threadIdx.x;
    red[i] = g_me[i] * (float)g_ce[i];
    __syncthreads();
    for (int s = 64; s > 0; s >>= 1) {
        if (i < s) red[i] += red[i + s];
        __syncthreads();
    }
    if (i == 0) {
        out[4 * T_TOKENS] = red[0] * ((float)N_EXP /
                              ((float)T_TOKENS * (float)T_TOKENS));
    }
}

extern "C" void kernel_launch(void* const* d_in, const int* in_sizes, int n_in,
                              void* d_out, int out_size) {
    const float* inp = (const float*)d_in[0];
    const float* wg  = (const float*)d_in[1];
    float* out = (float*)d_out;

    prep_b_kernel<<<(N_EXP * D_MODEL / 4 + 255) / 256, 256>>>(wg);
    init_kernel<<<1, 128>>>();

    cudaFuncSetAttribute(gate_kernel,
                         cudaFuncAttributeMaxDynamicSharedMemorySize,
                         SMEM_TOTAL);
    gate_kernel<<<T_TOKENS / BM, TPB, SMEM_TOTAL>>>(inp, out);

    loss_kernel<<<1, N_EXP>>>(out);
}

// round 10
// speedup vs baseline: 1.6464x; 1.1143x over previous
#include <cuda_runtime.h>
#include <cuda_fp16.h>
#include <math.h>
#include <stdint.h>

// ---------------- Problem constants ----------------
#define T_TOKENS 16384
#define D_MODEL  4096
#define N_EXP    128

// ---------------- GEMM config ----------------
#define BM   128
#define BN   128
#define CK   64                 // K per chunk (64 fp16 = 128B row)
#define NCHUNK (D_MODEL / CK)   // 64
#define TPB  640                // 16 consumer warps (4x4) + 4 producer warps

// smem: two 64KB stages; each: Ah Al Bh Bl (16KB each, 128 rows x 128B)
#define STAGE_BYTES 65536
#define OFF_AH 0
#define OFF_AL 16384
#define OFF_BH 32768
#define OFF_BL 49152
#define SMEM_TOTAL (2 * STAGE_BYTES)   // 131072

#define LS_STRIDE 132
#define SWZ(b) ((b) ^ (((b) >> 3) & 0x70))

// Named barriers (count = all 640 threads)
#define BAR_FULL0  1
#define BAR_FULL1  2
#define BAR_EMPTY0 3
#define BAR_EMPTY1 4
#define BAR_SYNC(id)   asm volatile("bar.sync %0, %1;"   :: "r"(id), "r"(TPB) : "memory")
#define BAR_ARRIVE(id) asm volatile("bar.arrive %0, %1;" :: "r"(id), "r"(TPB) : "memory")

// ---------------- sm_80-level PTX helpers ----------------
__device__ __forceinline__ uint32_t smem_to_u32(const void* p) {
    uint32_t a;
    asm("{ .reg .u64 t; cvta.to.shared.u64 t, %1; cvt.u32.u64 %0, t; }"
        : "=r"(a) : "l"(p));
    return a;
}
#define LDSM4(r0, r1, r2, r3, addr) \
    asm volatile("ldmatrix.sync.aligned.m8n8.x4.shared.b16 {%0,%1,%2,%3}, [%4];" \
        : "=r"(r0), "=r"(r1), "=r"(r2), "=r"(r3) : "r"(addr))
#define MMA16816(c, a, b0, b1) \
    asm volatile("mma.sync.aligned.m16n8k16.row.col.f32.f16.f16.f32 " \
        "{%0,%1,%2,%3},{%4,%5,%6,%7},{%8,%9},{%0,%1,%2,%3};" \
        : "+f"((c)[0]), "+f"((c)[1]), "+f"((c)[2]), "+f"((c)[3]) \
        : "r"((a)[0]), "r"((a)[1]), "r"((a)[2]), "r"((a)[3]), "r"(b0), "r"(b1))
__device__ __forceinline__ void cp16(uint32_t dst, const void* src) {
    asm volatile("cp.async.cg.shared.global [%0], [%1], 16;"
                 :: "r"(dst), "l"(src));
}
#define CP_COMMIT() asm volatile("cp.async.commit_group;" ::: "memory")
#define CP_WAIT0()  asm volatile("cp.async.wait_group 0;" ::: "memory")

// ---------------- Global scratch ----------------
__device__ float g_me[N_EXP];
__device__ int   g_ce[N_EXP];
__device__ __half g_Bh[N_EXP * D_MODEL];
__device__ __half g_Bl[N_EXP * D_MODEL];

__global__ void init_kernel() {
    int i = threadIdx.x;
    if (i < N_EXP) { g_me[i] = 0.0f; g_ce[i] = 0; }
}

// fp16 2-way split, UNSCALED residual: f = h + l (l may be subnormal)
__device__ __forceinline__ void split2(float f, __half& h, __half& l) {
    h = __float2half_rn(f);
    l = __float2half_rn(f - __half2float(h));
}
__device__ __forceinline__ uint32_t pack2h(__half a, __half b) {
    return (uint32_t)__half_as_ushort(a) |
           ((uint32_t)__half_as_ushort(b) << 16);
}

__global__ void prep_b_kernel(const float* __restrict__ wg) {
    int idx = blockIdx.x * blockDim.x + threadIdx.x;  // 0..131071
    float4 v = ((const float4*)wg)[idx];
    float f[4] = {v.x, v.y, v.z, v.w};
    __half h[4], l[4];
#pragma unroll
    for (int q = 0; q < 4; q++) split2(f[q], h[q], l[q]);
    ((uint2*)g_Bh)[idx] = make_uint2(pack2h(h[0], h[1]), pack2h(h[2], h[3]));
    ((uint2*)g_Bl)[idx] = make_uint2(pack2h(l[0], l[1]), pack2h(l[2], l[3]));
}

// top-2: (v1,i1) >= (v2,i2); ties -> smaller index (jax top_k semantics)
__device__ __forceinline__ void top2_upd(float& v1, int& i1, float& v2, int& i2,
                                         float v, int i) {
    if (v > v1 || (v == v1 && i < i1)) {
        v2 = v1; i2 = i1; v1 = v; i1 = i;
    } else if (v > v2 || (v == v2 && i < i2)) {
        v2 = v; i2 = i;
    }
}

__global__ void __launch_bounds__(TPB, 1)
gate_kernel(const float* __restrict__ A, float* __restrict__ out) {
    extern __shared__ char smem[];
    const uint32_t smem_u = smem_to_u32(smem);
    const int tid  = threadIdx.x;
    const int wid  = tid >> 5;
    const int lane = tid & 31;
    const int row0 = blockIdx.x * BM;

    float acc[2][4][4];   // warp tile M=32 (2x16), N=32 (4x8)

    if (wid < 16) {
        // ================= CONSUMERS: 4(M) x 4(N) warp grid =================
        const int mw = wid >> 2;          // 0..3 -> M offset 32*mw
        const int nw = wid & 3;           // 0..3 -> N offset 32*nw
        const int a_mrow = (lane & 7) + ((lane >> 3) & 1) * 8;
        const int a_cofs = ((lane >> 4) & 1) * 16;
        const int b_nrow = (lane & 7) + ((lane >> 4) & 1) * 8;
        const int b_cofs = ((lane >> 3) & 1) * 16;

#pragma unroll
        for (int i = 0; i < 2; i++)
#pragma unroll
            for (int j = 0; j < 4; j++)
#pragma unroll
                for (int q = 0; q < 4; q++) acc[i][j][q] = 0.0f;

        for (int c = 0; c < NCHUNK; c++) {
            const int s = c & 1;
            const uint32_t cur = smem_u + s * STAGE_BYTES;
            BAR_SYNC(s == 0 ? BAR_FULL0 : BAR_FULL1);

#pragma unroll 1
            for (int ks = 0; ks < 4; ks++) {
                const int kb = ks * 32;
                // B fragments: h and l parts (N=32 -> 2 LDSM4 each)
                uint32_t bfh[8], bfl[8];
#pragma unroll
                for (int q = 0; q < 2; q++) {
                    uint32_t bsw = SWZ((uint32_t)((nw * 32 + q * 16 + b_nrow) * 128 + kb + b_cofs));
                    LDSM4(bfh[q*4+0], bfh[q*4+1], bfh[q*4+2], bfh[q*4+3], cur + OFF_BH + bsw);
                    LDSM4(bfl[q*4+0], bfl[q*4+1], bfl[q*4+2], bfl[q*4+3], cur + OFF_BL + bsw);
                }
                // A-h fragments (M=32 -> 2 LDSM4)
                uint32_t af[8];
#pragma unroll
                for (int tm = 0; tm < 2; tm++) {
                    uint32_t asw = SWZ((uint32_t)((mw * 32 + tm * 16 + a_mrow) * 128 + kb + a_cofs));
                    LDSM4(af[tm*4+0], af[tm*4+1], af[tm*4+2], af[tm*4+3], cur + OFF_AH + asw);
                }
                // ah*bh and ah*bl -> acc
#pragma unroll
                for (int tm = 0; tm < 2; tm++)
#pragma unroll
                    for (int tn = 0; tn < 4; tn++) {
                        int bq = (tn >> 1) * 4 + (tn & 1) * 2;
                        MMA16816(acc[tm][tn], &af[tm*4], bfh[bq], bfh[bq+1]);
                        MMA16816(acc[tm][tn], &af[tm*4], bfl[bq], bfl[bq+1]);
                    }
                // A-l fragments (reuse af regs)
#pragma unroll
                for (int tm = 0; tm < 2; tm++) {
                    uint32_t asw = SWZ((uint32_t)((mw * 32 + tm * 16 + a_mrow) * 128 + kb + a_cofs));
                    LDSM4(af[tm*4+0], af[tm*4+1], af[tm*4+2], af[tm*4+3], cur + OFF_AL + asw);
                }
                // al*bh -> acc
#pragma unroll
                for (int tm = 0; tm < 2; tm++)
#pragma unroll
                    for (int tn = 0; tn < 4; tn++) {
                        int bq = (tn >> 1) * 4 + (tn & 1) * 2;
                        MMA16816(acc[tm][tn], &af[tm*4], bfh[bq], bfh[bq+1]);
                    }
            }
            BAR_ARRIVE(s == 0 ? BAR_EMPTY0 : BAR_EMPTY1);
        }
    } else {
        // ================= PRODUCERS: 4 warps, 128 threads =================
        const int ptid = tid - 512;   // 0..127
        for (int c = 0; c < NCHUNK; c++) {
            const int s = c & 1;
            char* stg = smem + s * STAGE_BYTES;
            const uint32_t stg_u = smem_u + s * STAGE_BYTES;
            const int k0 = c * CK;

            if (c >= 2) BAR_SYNC(s == 0 ? BAR_EMPTY0 : BAR_EMPTY1);

            // B tiles via cp.async (in flight during A work)
#pragma unroll
            for (int i = 0; i < 8; i++) {
                int idx = ptid + i * 128;          // 0..1023
                int r   = idx >> 3;
                int c16 = (idx & 7) * 16;
                size_t g = (size_t)r * D_MODEL + k0 + (c16 >> 1);
                uint32_t sw = SWZ((uint32_t)(r * 128 + c16));
                cp16(stg_u + OFF_BH + sw, g_Bh + g);
                cp16(stg_u + OFF_BL + sw, g_Bl + g);
            }
            CP_COMMIT();

            // A: LDG -> split2 -> STS, 2 batches of 8 float4 (reg budget 102)
#pragma unroll
            for (int bat = 0; bat < 2; bat++) {
                float4 aval[8];
#pragma unroll
                for (int i = 0; i < 8; i++) {
                    int idx = ptid + (bat * 8 + i) * 128;   // 0..2047
                    int r   = idx >> 4;
                    int col = (idx & 15) << 2;
                    aval[i] = *(const float4*)(A + (size_t)(row0 + r) * D_MODEL + k0 + col);
                }
#pragma unroll
                for (int i = 0; i < 8; i++) {
                    int idx = ptid + (bat * 8 + i) * 128;
                    int r   = idx >> 4;
                    int col = (idx & 15) << 2;
                    float f[4] = {aval[i].x, aval[i].y, aval[i].z, aval[i].w};
                    __half h[4], l[4];
#pragma unroll
                    for (int q = 0; q < 4; q++) split2(f[q], h[q], l[q]);
                    uint32_t sw = SWZ((uint32_t)(r * 128 + col * 2));
                    *(uint2*)(stg + OFF_AH + sw) = make_uint2(pack2h(h[0], h[1]), pack2h(h[2], h[3]));
                    *(uint2*)(stg + OFF_AL + sw) = make_uint2(pack2h(l[0], l[1]), pack2h(l[2], l[3]));
                }
            }
            CP_WAIT0();
            BAR_ARRIVE(s == 0 ? BAR_FULL0 : BAR_FULL1);
        }
    }

    __syncthreads();   // all 640 threads; stages now free -> repurpose as Ls

    float* Ls  = (float*)smem;
    float* sMe = (float*)(smem + BM * LS_STRIDE * 4);

    if (wid < 16) {
        const int mw = wid >> 2, nw = wid & 3;
        const int gid = lane >> 2, tig = lane & 3;
#pragma unroll
        for (int tm = 0; tm < 2; tm++)
#pragma unroll
            for (int tn = 0; tn < 4; tn++) {
                int r_ = mw * 32 + tm * 16 + gid;
                int c_ = nw * 32 + tn * 8 + tig * 2;
                Ls[r_ * LS_STRIDE + c_]           = acc[tm][tn][0];
                Ls[r_ * LS_STRIDE + c_ + 1]       = acc[tm][tn][1];
                Ls[(r_ + 8) * LS_STRIDE + c_]     = acc[tm][tn][2];
                Ls[(r_ + 8) * LS_STRIDE + c_ + 1] = acc[tm][tn][3];
            }
    }
    if (tid >= 512 && tid < 512 + N_EXP) sMe[tid - 512] = 0.0f;
    __syncthreads();

    // ---- epilogue: one warp per token, 20 warps stride over 128 tokens ----
    const float inv_temp = 1.0f / 0.3f;
    for (int t = wid; t < BM; t += 20) {
        float v[4]; int ix[4];
#pragma unroll
        for (int q = 0; q < 4; q++) {
            ix[q] = lane + q * 32;
            v[q]  = Ls[t * LS_STRIDE + ix[q]];
        }
        float v1 = -INFINITY, v2 = -INFINITY;
        int   i1 = N_EXP, i2 = N_EXP;
#pragma unroll
        for (int q = 0; q < 4; q++) top2_upd(v1, i1, v2, i2, v[q], ix[q]);
#pragma unroll
        for (int off = 16; off > 0; off >>= 1) {
            float ov1 = __shfl_xor_sync(0xffffffffu, v1, off);
            int   oi1 = __shfl_xor_sync(0xffffffffu, i1, off);
            float ov2 = __shfl_xor_sync(0xffffffffu, v2, off);
            int   oi2 = __shfl_xor_sync(0xffffffffu, i2, off);
            top2_upd(v1, i1, v2, i2, ov1, oi1);
            top2_upd(v1, i1, v2, i2, ov2, oi2);
        }
        float p[4], zl = 0.0f;
#pragma unroll
        for (int q = 0; q < 4; q++) {
            p[q] = expf((v[q] - v1) * inv_temp);
            zl += p[q];
        }
#pragma unroll
        for (int off = 16; off > 0; off >>= 1)
            zl += __shfl_xor_sync(0xffffffffu, zl, off);
        float invZ = 1.0f / zl;
#pragma unroll
        for (int q = 0; q < 4; q++)
            atomicAdd(&sMe[ix[q]], p[q] * invZ);

        if (lane == 0) {
            int tok = row0 + t;
            out[tok * 2 + 0] = (float)i1;
            out[tok * 2 + 1] = (float)i2;
            float e  = expf(v2 - v1);
            float g1 = e / (1.0f + e);
            out[2 * T_TOKENS + tok * 2 + 0] = 1.0f - g1;
            out[2 * T_TOKENS + tok * 2 + 1] = g1;
            atomicAdd(&g_ce[i1], 1);
        }
    }
    __syncthreads();
    if (tid < N_EXP) atomicAdd(&g_me[tid], sMe[tid]);
}

__global__ void loss_kernel(float* __restrict__ out) {
    __shared__ float red[N_EXP];
    int i = threadIdx.x;
    red[i] = g_me[i] * (float)g_ce[i];
    __syncthreads();
    for (int s = 64; s > 0; s >>= 1) {
        if (i < s) red[i] += red[i + s];
        __syncthreads();
    }
    if (i == 0) {
        out[4 * T_TOKENS] = red[0] * ((float)N_EXP /
                              ((float)T_TOKENS * (float)T_TOKENS));
    }
}

extern "C" void kernel_launch(void* const* d_in, const int* in_sizes, int n_in,
                              void* d_out, int out_size) {
    const float* inp = (const float*)d_in[0];
    const float* wg  = (const float*)d_in[1];
    float* out = (float*)d_out;

    prep_b_kernel<<<(N_EXP * D_MODEL / 4 + 255) / 256, 256>>>(wg);
    init_kernel<<<1, 128>>>();

    cudaFuncSetAttribute(gate_kernel,
                         cudaFuncAttributeMaxDynamicSharedMemorySize,
                         SMEM_TOTAL);
    gate_kernel<<<T_TOKENS / BM, TPB, SMEM_TOTAL>>>(inp, out);

    loss_kernel<<<1, N_EXP>>>(out);
}